// round 15
// baseline (speedup 1.0000x reference)
#include <cuda_runtime.h>
#include <cuda_bf16.h>
#include <cstdint>

// ---------------------------------------------------------------------------
// MultiHeadedAttention: B=2, S=2048, H=16, d_k=64, d_model=1024, fp32.
// R14: pre-converted bf16 hi/lo operands everywhere + cp.async 2-stage
// pipelined projection GEMMs. Flash core unchanged (epilogue now emits
// bf16 hi/lo attn for the output projection).
// ---------------------------------------------------------------------------

#define B_  2
#define S_  2048
#define H_  16
#define DK  64
#define DM  1024
#define M_  (B_ * S_)   // 4096

#define QKV_ELEMS ((size_t)B_ * H_ * S_ * DK)
__device__ __align__(16) __nv_bfloat16 g_Qhi[QKV_ELEMS];  // pre-scaled by 1/8
__device__ __align__(16) __nv_bfloat16 g_Qlo[QKV_ELEMS];
__device__ __align__(16) __nv_bfloat16 g_Khi[QKV_ELEMS];
__device__ __align__(16) __nv_bfloat16 g_Klo[QKV_ELEMS];
__device__ __align__(16) __nv_bfloat16 g_Vhi[QKV_ELEMS];
__device__ __align__(16) __nv_bfloat16 g_Vlo[QKV_ELEMS];

// pre-converted inputs (query/key/value) and weights (Wq/Wk/Wv/Wo)
__device__ __align__(16) __nv_bfloat16 g_Xhi[3 * (size_t)M_ * DM];
__device__ __align__(16) __nv_bfloat16 g_Xlo[3 * (size_t)M_ * DM];
__device__ __align__(16) __nv_bfloat16 g_Whi[4 * (size_t)DM * DM];
__device__ __align__(16) __nv_bfloat16 g_Wlo[4 * (size_t)DM * DM];

// attn output (merged-head) as bf16 hi/lo
__device__ __align__(16) __nv_bfloat16 g_ATTNhi[(size_t)M_ * DM];
__device__ __align__(16) __nv_bfloat16 g_ATTNlo[(size_t)M_ * DM];

// ===========================================================================
// helpers
// ===========================================================================
__device__ __forceinline__ uint32_t smem_u32(const void* p) {
    uint32_t a;
    asm("{ .reg .u64 t; cvta.to.shared.u64 t, %1; cvt.u32.u64 %0, t; }"
        : "=r"(a) : "l"(p));
    return a;
}
__device__ __forceinline__ void ldsm_x4(uint32_t (&r)[4], uint32_t addr) {
    asm volatile("ldmatrix.sync.aligned.m8n8.x4.shared.b16 {%0,%1,%2,%3}, [%4];"
        : "=r"(r[0]), "=r"(r[1]), "=r"(r[2]), "=r"(r[3]) : "r"(addr));
}
__device__ __forceinline__ void ldsm_x4_t(uint32_t (&r)[4], uint32_t addr) {
    asm volatile("ldmatrix.sync.aligned.m8n8.x4.trans.shared.b16 {%0,%1,%2,%3}, [%4];"
        : "=r"(r[0]), "=r"(r[1]), "=r"(r[2]), "=r"(r[3]) : "r"(addr));
}
__device__ __forceinline__ void mma_bf16(float (&d)[4], const uint32_t (&a)[4],
                                         uint32_t b0, uint32_t b1) {
    asm volatile(
        "mma.sync.aligned.m16n8k16.row.col.f32.bf16.bf16.f32 "
        "{%0,%1,%2,%3}, {%4,%5,%6,%7}, {%8,%9}, {%0,%1,%2,%3};"
        : "+f"(d[0]), "+f"(d[1]), "+f"(d[2]), "+f"(d[3])
        : "r"(a[0]), "r"(a[1]), "r"(a[2]), "r"(a[3]), "r"(b0), "r"(b1));
}
__device__ __forceinline__ uint32_t pack_hl(float x0, float x1, uint32_t& lo) {
    __nv_bfloat16 h0 = __float2bfloat16(x0), h1 = __float2bfloat16(x1);
    __nv_bfloat16 l0 = __float2bfloat16(x0 - __bfloat162float(h0));
    __nv_bfloat16 l1 = __float2bfloat16(x1 - __bfloat162float(h1));
    lo = (uint32_t)__bfloat16_as_ushort(l0) | ((uint32_t)__bfloat16_as_ushort(l1) << 16);
    return (uint32_t)__bfloat16_as_ushort(h0) | ((uint32_t)__bfloat16_as_ushort(h1) << 16);
}

#define CP_ASYNC16(saddr, gptr) \
    asm volatile("cp.async.cg.shared.global [%0], [%1], 16;" \
                 :: "r"(saddr), "l"(gptr))
#define CP_COMMIT() asm volatile("cp.async.commit_group;" ::: "memory")

// ===========================================================================
// conversion kernels (fp32 -> hi/lo bf16), grid-stride-free elementwise
// ===========================================================================
__global__ __launch_bounds__(256) void conv_in_kernel(
    const float* __restrict__ q, const float* __restrict__ k,
    const float* __restrict__ v)
{
    const float* src = (blockIdx.z == 0) ? q : (blockIdx.z == 1) ? k : v;
    __nv_bfloat16* hi = g_Xhi + (size_t)blockIdx.z * M_ * DM;
    __nv_bfloat16* lo = g_Xlo + (size_t)blockIdx.z * M_ * DM;
    size_t i = ((size_t)blockIdx.x * 256 + threadIdx.x) * 4;
    float4 x = *(const float4*)(src + i);
    uint32_t l0, l1;
    uint32_t h0 = pack_hl(x.x, x.y, l0);
    uint32_t h1 = pack_hl(x.z, x.w, l1);
    *(uint2*)&hi[i] = make_uint2(h0, h1);
    *(uint2*)&lo[i] = make_uint2(l0, l1);
}

__global__ __launch_bounds__(256) void conv_w_kernel(
    const float* __restrict__ wq, const float* __restrict__ wk,
    const float* __restrict__ wv, const float* __restrict__ wo)
{
    const float* src = (blockIdx.z == 0) ? wq : (blockIdx.z == 1) ? wk
                     : (blockIdx.z == 2) ? wv : wo;
    __nv_bfloat16* hi = g_Whi + (size_t)blockIdx.z * DM * DM;
    __nv_bfloat16* lo = g_Wlo + (size_t)blockIdx.z * DM * DM;
    size_t i = ((size_t)blockIdx.x * 256 + threadIdx.x) * 4;
    float4 x = *(const float4*)(src + i);
    uint32_t l0, l1;
    uint32_t h0 = pack_hl(x.x, x.y, l0);
    uint32_t h1 = pack_hl(x.z, x.w, l1);
    *(uint2*)&hi[i] = make_uint2(h0, h1);
    *(uint2*)&lo[i] = make_uint2(l0, l1);
}

// ===========================================================================
// Pipelined bf16 GEMM: Y[128,128] tile of A[M,1024] @ B[1024,1024]^T.
// cp.async 2-stage double buffer; K chunk = 64 (tile 128 x 128 B).
// ===========================================================================
#define KC        64
#define NCHUNK    (DM / KC)
#define ROWB      144
#define TILE_B    (128 * ROWB)
#define OFF_AHI   0
#define OFF_ALO   TILE_B
#define OFF_BHI   (2 * TILE_B)
#define OFF_BLO   (3 * TILE_B)
#define STAGE_B   (4 * TILE_B)        // 73728 B
#define GEMM_SMEM (2 * STAGE_B)       // 147456 B -> 1 CTA/SM

__device__ __forceinline__ void issue_stage(
    const __nv_bfloat16* __restrict__ Ahi, const __nv_bfloat16* __restrict__ Alo,
    const __nv_bfloat16* __restrict__ Bhi, const __nv_bfloat16* __restrict__ Blo,
    int m0, int n0, int k0, uint32_t sbase, int tid)
{
    #pragma unroll
    for (int v = tid; v < 1024; v += 256) {
        int row = v >> 3, ch = v & 7;
        uint32_t soff = (uint32_t)row * ROWB + (uint32_t)ch * 16;
        size_t ga = (size_t)(m0 + row) * DM + k0 + ch * 8;
        size_t gb = (size_t)(n0 + row) * DM + k0 + ch * 8;
        CP_ASYNC16(sbase + OFF_AHI + soff, Ahi + ga);
        CP_ASYNC16(sbase + OFF_ALO + soff, Alo + ga);
        CP_ASYNC16(sbase + OFF_BHI + soff, Bhi + gb);
        CP_ASYNC16(sbase + OFF_BLO + soff, Blo + gb);
    }
}

__device__ __forceinline__ void mma_chunk2(
    uint32_t sb, int warp_m, int warp_n, int lane, float d[4][4][4])
{
    const uint32_t aRow = (uint32_t)(warp_m * 64 + (lane & 15)) * ROWB
                        + ((lane >> 4) & 1) * 16;
    const uint32_t bRow = (uint32_t)(warp_n * 32 + (lane & 7)) * ROWB
                        + ((lane >> 3) & 1) * 16;
    #pragma unroll
    for (int ks = 0; ks < 4; ks++) {
        const uint32_t kb = (uint32_t)ks * 32;
        uint32_t bh[4][2], bl[4][2];
        #pragma unroll
        for (int ni = 0; ni < 4; ni++) {
            uint32_t baddr = sb + OFF_BHI + bRow + (uint32_t)ni * 8 * ROWB + kb;
            asm volatile("ldmatrix.sync.aligned.m8n8.x2.shared.b16 {%0,%1}, [%2];"
                : "=r"(bh[ni][0]), "=r"(bh[ni][1]) : "r"(baddr));
            asm volatile("ldmatrix.sync.aligned.m8n8.x2.shared.b16 {%0,%1}, [%2];"
                : "=r"(bl[ni][0]), "=r"(bl[ni][1]) : "r"(baddr + (OFF_BLO - OFF_BHI)));
        }
        #pragma unroll
        for (int mi = 0; mi < 4; mi++) {
            uint32_t aaddr = sb + OFF_AHI + aRow + (uint32_t)mi * 16 * ROWB + kb;
            uint32_t ah[4], al[4];
            ldsm_x4(ah, aaddr);
            ldsm_x4(al, aaddr + (OFF_ALO - OFF_AHI));
            #pragma unroll
            for (int ni = 0; ni < 4; ni++) {
                mma_bf16(d[mi][ni], ah, bh[ni][0], bh[ni][1]);
                mma_bf16(d[mi][ni], ah, bl[ni][0], bl[ni][1]);
                mma_bf16(d[mi][ni], al, bh[ni][0], bh[ni][1]);
            }
        }
    }
}

__device__ __forceinline__ void gemm_bf16_mainloop(
    const __nv_bfloat16* __restrict__ Ahi, const __nv_bfloat16* __restrict__ Alo,
    const __nv_bfloat16* __restrict__ Bhi, const __nv_bfloat16* __restrict__ Blo,
    int m0, int n0, uint32_t smem_base,
    int warp_m, int warp_n, int lane, int tid, float d[4][4][4])
{
    issue_stage(Ahi, Alo, Bhi, Blo, m0, n0, 0, smem_base, tid);
    CP_COMMIT();
    for (int c = 0; c < NCHUNK; c++) {
        if (c + 1 < NCHUNK) {
            issue_stage(Ahi, Alo, Bhi, Blo, m0, n0, (c + 1) * KC,
                        smem_base + ((c + 1) & 1) * STAGE_B, tid);
            CP_COMMIT();
            asm volatile("cp.async.wait_group 1;" ::: "memory");
        } else {
            asm volatile("cp.async.wait_group 0;" ::: "memory");
        }
        __syncthreads();
        mma_chunk2(smem_base + (c & 1) * STAGE_B, warp_m, warp_n, lane, d);
        __syncthreads();
    }
}

// --------------------------- qkv projection --------------------------------
__global__ __launch_bounds__(256, 1) void qkv_mma_kernel(
    const float* __restrict__ bq, const float* __restrict__ bk,
    const float* __restrict__ bv)
{
    extern __shared__ char smem[];
    const uint32_t smem_base = smem_u32(smem);
    const int tid = threadIdx.x;
    const int lane = tid & 31, w = tid >> 5;
    const int warp_m = w & 1, warp_n = w >> 1;
    const int z = blockIdx.z;

    const __nv_bfloat16* Ahi = g_Xhi + (size_t)z * M_ * DM;
    const __nv_bfloat16* Alo = g_Xlo + (size_t)z * M_ * DM;
    const __nv_bfloat16* Bhi = g_Whi + (size_t)z * DM * DM;
    const __nv_bfloat16* Blo = g_Wlo + (size_t)z * DM * DM;
    const float* bias = (z == 0) ? bq : (z == 1) ? bk : bv;
    __nv_bfloat16* ghi = (z == 0) ? g_Qhi : (z == 1) ? g_Khi : g_Vhi;
    __nv_bfloat16* glo = (z == 0) ? g_Qlo : (z == 1) ? g_Klo : g_Vlo;
    const float scale = (z == 0) ? 0.125f : 1.0f;

    float d[4][4][4];
    #pragma unroll
    for (int i = 0; i < 4; i++)
        #pragma unroll
        for (int j = 0; j < 4; j++)
            #pragma unroll
            for (int k = 0; k < 4; k++) d[i][j][k] = 0.f;

    const int m0 = blockIdx.x * 128;
    const int n0 = blockIdx.y * 128;
    gemm_bf16_mainloop(Ahi, Alo, Bhi, Blo, m0, n0, smem_base,
                       warp_m, warp_n, lane, tid, d);

    #pragma unroll
    for (int mi = 0; mi < 4; mi++) {
        int r  = m0 + warp_m * 64 + mi * 16 + (lane >> 2);
        int bb = r >> 11;
        int s  = r & (S_ - 1);
        #pragma unroll
        for (int ni = 0; ni < 4; ni++) {
            int c  = n0 + warp_n * 32 + ni * 8 + (lane & 3) * 2;
            int h  = c >> 6;
            int dd = c & 63;
            size_t idx0 = ((size_t)(bb * H_ + h) * S_ + s) * DK + dd;
            size_t idx1 = idx0 + 8 * DK;
            float x0 = (d[mi][ni][0] + bias[c])     * scale;
            float x1 = (d[mi][ni][1] + bias[c + 1]) * scale;
            float x2 = (d[mi][ni][2] + bias[c])     * scale;
            float x3 = (d[mi][ni][3] + bias[c + 1]) * scale;
            uint32_t lo0, lo1, hi0, hi1;
            hi0 = pack_hl(x0, x1, lo0);
            hi1 = pack_hl(x2, x3, lo1);
            *(uint32_t*)&ghi[idx0] = hi0;
            *(uint32_t*)&glo[idx0] = lo0;
            *(uint32_t*)&ghi[idx1] = hi1;
            *(uint32_t*)&glo[idx1] = lo1;
        }
    }
}

// --------------------------- output projection -----------------------------
__global__ __launch_bounds__(256, 1) void out_mma_kernel(
    const float* __restrict__ bo, float* __restrict__ out)
{
    extern __shared__ char smem[];
    const uint32_t smem_base = smem_u32(smem);
    const int tid = threadIdx.x;
    const int lane = tid & 31, w = tid >> 5;
    const int warp_m = w & 1, warp_n = w >> 1;

    float d[4][4][4];
    #pragma unroll
    for (int i = 0; i < 4; i++)
        #pragma unroll
        for (int j = 0; j < 4; j++)
            #pragma unroll
            for (int k = 0; k < 4; k++) d[i][j][k] = 0.f;

    const int m0 = blockIdx.x * 128;
    const int n0 = blockIdx.y * 128;
    gemm_bf16_mainloop(g_ATTNhi, g_ATTNlo,
                       g_Whi + (size_t)3 * DM * DM, g_Wlo + (size_t)3 * DM * DM,
                       m0, n0, smem_base, warp_m, warp_n, lane, tid, d);

    #pragma unroll
    for (int mi = 0; mi < 4; mi++) {
        int r = m0 + warp_m * 64 + mi * 16 + (lane >> 2);
        #pragma unroll
        for (int ni = 0; ni < 4; ni++) {
            int c = n0 + warp_n * 32 + ni * 8 + (lane & 3) * 2;
            float2 v0 = { d[mi][ni][0] + bo[c], d[mi][ni][1] + bo[c + 1] };
            float2 v1 = { d[mi][ni][2] + bo[c], d[mi][ni][3] + bo[c + 1] };
            *(float2*)&out[(size_t)r * DM + c]       = v0;
            *(float2*)&out[(size_t)(r + 8) * DM + c] = v1;
        }
    }
}

// ===========================================================================
// Flash attention on mma.sync (R13 core; epilogue now writes bf16 hi/lo)
// ===========================================================================
#define FROWB    144
#define F_KHI    0
#define F_KLO    (F_KHI + 64 * FROWB)
#define F_VHI    (F_KLO + 64 * FROWB)
#define F_VLO    (F_VHI + 64 * FROWB)
#define F_QHI    (F_VLO + 64 * FROWB)
#define F_QLO    (F_QHI + 128 * FROWB)
#define F_PHI    (F_QLO + 128 * FROWB)
#define F_PLO    (F_PHI + 128 * FROWB)
#define FLASH_SMEM (F_PLO + 128 * FROWB) // 110,592 B

__global__ __launch_bounds__(256, 2) void flash_mma_kernel(const int* __restrict__ mask)
{
    extern __shared__ char fsm[];
    const uint32_t base = smem_u32(fsm);
    const int tid  = threadIdx.x;
    const int lane = tid & 31;
    const int w    = tid >> 5;
    const int q0   = blockIdx.x * 128;
    const int h    = blockIdx.y;
    const int b    = blockIdx.z;

    const __nv_bfloat16* Qh = g_Qhi + (size_t)(b * H_ + h) * S_ * DK;
    const __nv_bfloat16* Ql = g_Qlo + (size_t)(b * H_ + h) * S_ * DK;
    const __nv_bfloat16* Kh = g_Khi + (size_t)(b * H_ + h) * S_ * DK;
    const __nv_bfloat16* Kl = g_Klo + (size_t)(b * H_ + h) * S_ * DK;
    const __nv_bfloat16* Vh = g_Vhi + (size_t)(b * H_ + h) * S_ * DK;
    const __nv_bfloat16* Vl = g_Vlo + (size_t)(b * H_ + h) * S_ * DK;
    const int* Mg = mask + (size_t)b * S_ * S_;

    #pragma unroll
    for (int v = tid; v < 1024; v += 256) {
        int row = v >> 3, ch = v & 7;
        uint32_t off = (uint32_t)row * FROWB + (uint32_t)ch * 16;
        *(uint4*)(fsm + F_QHI + off) = *(const uint4*)(Qh + (size_t)(q0 + row) * DK + ch * 8);
        *(uint4*)(fsm + F_QLO + off) = *(const uint4*)(Ql + (size_t)(q0 + row) * DK + ch * 8);
    }

    const uint32_t qbase = base + F_QHI + (uint32_t)(w * 16 + (lane & 15)) * FROWB
                         + ((lane >> 4) & 1) * 16;
    const uint32_t kbase = base + F_KHI + (uint32_t)(((lane >> 4) & 1) * 8 + (lane & 7)) * FROWB
                         + ((lane >> 3) & 1) * 16;
    const uint32_t pbase = base + F_PHI + (uint32_t)(w * 16 + (lane & 15)) * FROWB
                         + ((lane >> 4) & 1) * 16;
    const uint32_t vbase = base + F_VHI + (uint32_t)(((lane >> 3) & 1) * 8 + (lane & 7)) * FROWB
                         + ((lane >> 4) & 1) * 16;

    float m0r = -1e30f, m1r = -1e30f, l0r = 0.f, l1r = 0.f;
    float o[8][4];
    #pragma unroll
    for (int i = 0; i < 8; i++)
        #pragma unroll
        for (int j = 0; j < 4; j++) o[i][j] = 0.f;

    const int rg0 = q0 + w * 16 + (lane >> 2);
    const int cg  = (lane & 3) * 2;

    for (int n0t = 0; n0t < S_; n0t += 64) {
        #pragma unroll
        for (int v = tid; v < 512; v += 256) {
            int row = v >> 3, ch = v & 7;
            uint32_t off = (uint32_t)row * FROWB + (uint32_t)ch * 16;
            const size_t g = (size_t)(n0t + row) * DK + ch * 8;
            *(uint4*)(fsm + F_KHI + off) = *(const uint4*)(Kh + g);
            *(uint4*)(fsm + F_KLO + off) = *(const uint4*)(Kl + g);
            *(uint4*)(fsm + F_VHI + off) = *(const uint4*)(Vh + g);
            *(uint4*)(fsm + F_VLO + off) = *(const uint4*)(Vl + g);
        }
        __syncthreads();

        float s[8][4];
        #pragma unroll
        for (int i = 0; i < 8; i++)
            #pragma unroll
            for (int j = 0; j < 4; j++) s[i][j] = 0.f;

        #pragma unroll
        for (int ks = 0; ks < 4; ks++) {
            uint32_t aH[4], aL[4];
            ldsm_x4(aH, qbase + ks * 32);
            ldsm_x4(aL, qbase + (F_QLO - F_QHI) + ks * 32);
            #pragma unroll
            for (int nip = 0; nip < 4; nip++) {
                uint32_t kh[4], kl[4];
                uint32_t ka = kbase + (uint32_t)nip * 16 * FROWB + ks * 32;
                ldsm_x4(kh, ka);
                ldsm_x4(kl, ka + (F_KLO - F_KHI));
                mma_bf16(s[2 * nip],     aH, kh[0], kh[1]);
                mma_bf16(s[2 * nip],     aH, kl[0], kl[1]);
                mma_bf16(s[2 * nip],     aL, kh[0], kh[1]);
                mma_bf16(s[2 * nip + 1], aH, kh[2], kh[3]);
                mma_bf16(s[2 * nip + 1], aH, kl[2], kl[3]);
                mma_bf16(s[2 * nip + 1], aL, kh[2], kh[3]);
            }
        }

        #pragma unroll
        for (int ni = 0; ni < 8; ni++) {
            int c = n0t + ni * 8 + cg;
            int2 mm0 = *(const int2*)(Mg + (size_t)rg0 * S_ + c);
            int2 mm1 = *(const int2*)(Mg + (size_t)(rg0 + 8) * S_ + c);
            if (mm0.x == 0) s[ni][0] = -1e9f;
            if (mm0.y == 0) s[ni][1] = -1e9f;
            if (mm1.x == 0) s[ni][2] = -1e9f;
            if (mm1.y == 0) s[ni][3] = -1e9f;
        }

        float mx0 = -1e30f, mx1 = -1e30f;
        #pragma unroll
        for (int ni = 0; ni < 8; ni++) {
            mx0 = fmaxf(mx0, fmaxf(s[ni][0], s[ni][1]));
            mx1 = fmaxf(mx1, fmaxf(s[ni][2], s[ni][3]));
        }
        mx0 = fmaxf(mx0, __shfl_xor_sync(0xffffffffu, mx0, 1));
        mx0 = fmaxf(mx0, __shfl_xor_sync(0xffffffffu, mx0, 2));
        mx1 = fmaxf(mx1, __shfl_xor_sync(0xffffffffu, mx1, 1));
        mx1 = fmaxf(mx1, __shfl_xor_sync(0xffffffffu, mx1, 2));

        float mn0 = fmaxf(m0r, mx0), mn1 = fmaxf(m1r, mx1);
        float f0 = __expf(m0r - mn0), f1 = __expf(m1r - mn1);
        m0r = mn0; m1r = mn1;

        float sum0 = 0.f, sum1 = 0.f;
        #pragma unroll
        for (int ni = 0; ni < 8; ni++) {
            s[ni][0] = __expf(s[ni][0] - mn0);
            s[ni][1] = __expf(s[ni][1] - mn0);
            s[ni][2] = __expf(s[ni][2] - mn1);
            s[ni][3] = __expf(s[ni][3] - mn1);
            sum0 += s[ni][0] + s[ni][1];
            sum1 += s[ni][2] + s[ni][3];
        }
        sum0 += __shfl_xor_sync(0xffffffffu, sum0, 1);
        sum0 += __shfl_xor_sync(0xffffffffu, sum0, 2);
        sum1 += __shfl_xor_sync(0xffffffffu, sum1, 1);
        sum1 += __shfl_xor_sync(0xffffffffu, sum1, 2);
        l0r = l0r * f0 + sum0;
        l1r = l1r * f1 + sum1;

        #pragma unroll
        for (int ni = 0; ni < 8; ni++) {
            o[ni][0] *= f0; o[ni][1] *= f0;
            o[ni][2] *= f1; o[ni][3] *= f1;
        }

        #pragma unroll
        for (int ni = 0; ni < 8; ni++) {
            uint32_t cbyte = (uint32_t)(ni * 8 + cg) * 2;
            uint32_t r0off = (uint32_t)(w * 16 + (lane >> 2)) * FROWB + cbyte;
            uint32_t lo0, lo1, hi0, hi1;
            hi0 = pack_hl(s[ni][0], s[ni][1], lo0);
            hi1 = pack_hl(s[ni][2], s[ni][3], lo1);
            *(uint32_t*)(fsm + F_PHI + r0off)             = hi0;
            *(uint32_t*)(fsm + F_PLO + r0off)             = lo0;
            *(uint32_t*)(fsm + F_PHI + r0off + 8 * FROWB) = hi1;
            *(uint32_t*)(fsm + F_PLO + r0off + 8 * FROWB) = lo1;
        }
        __syncwarp();

        #pragma unroll
        for (int ks = 0; ks < 4; ks++) {
            uint32_t pH[4], pL[4];
            ldsm_x4(pH, pbase + ks * 32);
            ldsm_x4(pL, pbase + (F_PLO - F_PHI) + ks * 32);
            #pragma unroll
            for (int nip = 0; nip < 4; nip++) {
                uint32_t vh[4], vl[4];
                uint32_t va = vbase + (uint32_t)ks * 16 * FROWB + (uint32_t)nip * 32;
                ldsm_x4_t(vh, va);
                ldsm_x4_t(vl, va + (F_VLO - F_VHI));
                mma_bf16(o[2 * nip],     pH, vh[0], vh[1]);
                mma_bf16(o[2 * nip],     pH, vl[0], vl[1]);
                mma_bf16(o[2 * nip],     pL, vh[0], vh[1]);
                mma_bf16(o[2 * nip + 1], pH, vh[2], vh[3]);
                mma_bf16(o[2 * nip + 1], pH, vl[2], vl[3]);
                mma_bf16(o[2 * nip + 1], pL, vh[2], vh[3]);
            }
        }
        __syncthreads();
    }

    // epilogue: normalize, write attn as bf16 hi/lo (merged-head layout)
    float inv0 = 1.0f / l0r, inv1 = 1.0f / l1r;
    #pragma unroll
    for (int ni = 0; ni < 8; ni++) {
        int dd = h * DK + ni * 8 + cg;
        size_t i0 = (size_t)(b * S_ + rg0) * DM + dd;
        size_t i1 = (size_t)(b * S_ + rg0 + 8) * DM + dd;
        uint32_t lo0, lo1, hi0, hi1;
        hi0 = pack_hl(o[ni][0] * inv0, o[ni][1] * inv0, lo0);
        hi1 = pack_hl(o[ni][2] * inv1, o[ni][3] * inv1, lo1);
        *(uint32_t*)&g_ATTNhi[i0] = hi0;
        *(uint32_t*)&g_ATTNlo[i0] = lo0;
        *(uint32_t*)&g_ATTNhi[i1] = hi1;
        *(uint32_t*)&g_ATTNlo[i1] = lo1;
    }
}

// ===========================================================================
extern "C" void kernel_launch(void* const* d_in, const int* in_sizes, int n_in,
                              void* d_out, int out_size)
{
    (void)in_sizes; (void)n_in; (void)out_size;
    const float* query = (const float*)d_in[0];
    const float* key   = (const float*)d_in[1];
    const float* value = (const float*)d_in[2];
    const int*   mask  = (const int*)d_in[3];
    const float* Wq    = (const float*)d_in[4];
    const float* bq    = (const float*)d_in[5];
    const float* Wk    = (const float*)d_in[6];
    const float* bk    = (const float*)d_in[7];
    const float* Wv    = (const float*)d_in[8];
    const float* bv    = (const float*)d_in[9];
    const float* Wo    = (const float*)d_in[10];
    const float* bo    = (const float*)d_in[11];
    float* out = (float*)d_out;

    cudaFuncSetAttribute(qkv_mma_kernel,
                         cudaFuncAttributeMaxDynamicSharedMemorySize, GEMM_SMEM);
    cudaFuncSetAttribute(out_mma_kernel,
                         cudaFuncAttributeMaxDynamicSharedMemorySize, GEMM_SMEM);
    cudaFuncSetAttribute(flash_mma_kernel,
                         cudaFuncAttributeMaxDynamicSharedMemorySize, FLASH_SMEM);

    // 0) pre-convert inputs and weights to bf16 hi/lo
    dim3 gci((M_ * DM) / 1024, 1, 3);      // (4096, 1, 3)
    conv_in_kernel<<<gci, 256>>>(query, key, value);
    dim3 gcw((DM * DM) / 1024, 1, 4);      // (1024, 1, 4)
    conv_w_kernel<<<gcw, 256>>>(Wq, Wk, Wv, Wo);

    // 1) QKV projections (cp.async pipelined bf16 GEMM)
    dim3 gproj(M_ / 128, DM / 128, 3);     // (32, 8, 3)
    qkv_mma_kernel<<<gproj, 256, GEMM_SMEM>>>(bq, bk, bv);

    // 2) Flash attention
    dim3 gflash(S_ / 128, H_, B_);         // (16, 16, 2)
    flash_mma_kernel<<<gflash, 256, FLASH_SMEM>>>(mask);

    // 3) Output projection
    dim3 gout(M_ / 128, DM / 128);         // (32, 8)
    out_mma_kernel<<<gout, 256, GEMM_SMEM>>>(bo, out);
}

// round 16
// speedup vs baseline: 1.1494x; 1.1494x over previous
#include <cuda_runtime.h>
#include <cuda_fp16.h>
#include <cstdint>

// ---------------------------------------------------------------------------
// MultiHeadedAttention: B=2, S=2048, H=16, d_k=64, d_model=1024, fp32.
// R16: fp16 hi/lo everywhere (tighter than bf16), 2-pass PV in flash
// (P as plain fp16), projection GEMMs back to 2 CTAs/SM single-stage
// cp.async with pre-converted operands.
// ---------------------------------------------------------------------------

#define B_  2
#define S_  2048
#define H_  16
#define DK  64
#define DM  1024
#define M_  (B_ * S_)   // 4096

#define QKV_ELEMS ((size_t)B_ * H_ * S_ * DK)
__device__ __align__(16) __half g_Qhi[QKV_ELEMS];  // pre-scaled by 1/8
__device__ __align__(16) __half g_Qlo[QKV_ELEMS];
__device__ __align__(16) __half g_Khi[QKV_ELEMS];
__device__ __align__(16) __half g_Klo[QKV_ELEMS];
__device__ __align__(16) __half g_Vhi[QKV_ELEMS];
__device__ __align__(16) __half g_Vlo[QKV_ELEMS];

__device__ __align__(16) __half g_Xhi[3 * (size_t)M_ * DM];
__device__ __align__(16) __half g_Xlo[3 * (size_t)M_ * DM];
__device__ __align__(16) __half g_Whi[4 * (size_t)DM * DM];
__device__ __align__(16) __half g_Wlo[4 * (size_t)DM * DM];

__device__ __align__(16) __half g_ATTNhi[(size_t)M_ * DM];
__device__ __align__(16) __half g_ATTNlo[(size_t)M_ * DM];

// ===========================================================================
// helpers
// ===========================================================================
__device__ __forceinline__ uint32_t smem_u32(const void* p) {
    uint32_t a;
    asm("{ .reg .u64 t; cvta.to.shared.u64 t, %1; cvt.u32.u64 %0, t; }"
        : "=r"(a) : "l"(p));
    return a;
}
__device__ __forceinline__ void ldsm_x4(uint32_t (&r)[4], uint32_t addr) {
    asm volatile("ldmatrix.sync.aligned.m8n8.x4.shared.b16 {%0,%1,%2,%3}, [%4];"
        : "=r"(r[0]), "=r"(r[1]), "=r"(r[2]), "=r"(r[3]) : "r"(addr));
}
__device__ __forceinline__ void ldsm_x4_t(uint32_t (&r)[4], uint32_t addr) {
    asm volatile("ldmatrix.sync.aligned.m8n8.x4.trans.shared.b16 {%0,%1,%2,%3}, [%4];"
        : "=r"(r[0]), "=r"(r[1]), "=r"(r[2]), "=r"(r[3]) : "r"(addr));
}
__device__ __forceinline__ void mma_f16(float (&d)[4], const uint32_t (&a)[4],
                                        uint32_t b0, uint32_t b1) {
    asm volatile(
        "mma.sync.aligned.m16n8k16.row.col.f32.f16.f16.f32 "
        "{%0,%1,%2,%3}, {%4,%5,%6,%7}, {%8,%9}, {%0,%1,%2,%3};"
        : "+f"(d[0]), "+f"(d[1]), "+f"(d[2]), "+f"(d[3])
        : "r"(a[0]), "r"(a[1]), "r"(a[2]), "r"(a[3]), "r"(b0), "r"(b1));
}
// fp16 hi/lo split of (x0, x1) -> packed uint32s
__device__ __forceinline__ uint32_t pack_hl(float x0, float x1, uint32_t& lo) {
    __half h0 = __float2half_rn(x0), h1 = __float2half_rn(x1);
    __half l0 = __float2half_rn(x0 - __half2float(h0));
    __half l1 = __float2half_rn(x1 - __half2float(h1));
    lo = (uint32_t)__half_as_ushort(l0) | ((uint32_t)__half_as_ushort(l1) << 16);
    return (uint32_t)__half_as_ushort(h0) | ((uint32_t)__half_as_ushort(h1) << 16);
}
__device__ __forceinline__ uint32_t pack_f16(float x0, float x1) {
    return (uint32_t)__half_as_ushort(__float2half_rn(x0))
         | ((uint32_t)__half_as_ushort(__float2half_rn(x1)) << 16);
}

#define CP_ASYNC16(saddr, gptr) \
    asm volatile("cp.async.cg.shared.global [%0], [%1], 16;" \
                 :: "r"(saddr), "l"(gptr))
#define CP_COMMIT() asm volatile("cp.async.commit_group;" ::: "memory")
#define CP_WAIT0()  asm volatile("cp.async.wait_group 0;" ::: "memory")

// ===========================================================================
// conversion kernels (fp32 -> hi/lo fp16)
// ===========================================================================
__global__ __launch_bounds__(256) void conv_in_kernel(
    const float* __restrict__ q, const float* __restrict__ k,
    const float* __restrict__ v)
{
    const float* src = (blockIdx.z == 0) ? q : (blockIdx.z == 1) ? k : v;
    __half* hi = g_Xhi + (size_t)blockIdx.z * M_ * DM;
    __half* lo = g_Xlo + (size_t)blockIdx.z * M_ * DM;
    size_t i = ((size_t)blockIdx.x * 256 + threadIdx.x) * 4;
    float4 x = *(const float4*)(src + i);
    uint32_t l0, l1;
    uint32_t h0 = pack_hl(x.x, x.y, l0);
    uint32_t h1 = pack_hl(x.z, x.w, l1);
    *(uint2*)&hi[i] = make_uint2(h0, h1);
    *(uint2*)&lo[i] = make_uint2(l0, l1);
}

__global__ __launch_bounds__(256) void conv_w_kernel(
    const float* __restrict__ wq, const float* __restrict__ wk,
    const float* __restrict__ wv, const float* __restrict__ wo)
{
    const float* src = (blockIdx.z == 0) ? wq : (blockIdx.z == 1) ? wk
                     : (blockIdx.z == 2) ? wv : wo;
    __half* hi = g_Whi + (size_t)blockIdx.z * DM * DM;
    __half* lo = g_Wlo + (size_t)blockIdx.z * DM * DM;
    size_t i = ((size_t)blockIdx.x * 256 + threadIdx.x) * 4;
    float4 x = *(const float4*)(src + i);
    uint32_t l0, l1;
    uint32_t h0 = pack_hl(x.x, x.y, l0);
    uint32_t h1 = pack_hl(x.z, x.w, l1);
    *(uint2*)&hi[i] = make_uint2(h0, h1);
    *(uint2*)&lo[i] = make_uint2(l0, l1);
}

// ===========================================================================
// fp16 GEMM: Y[128,128] tile of A[M,1024] @ B[1024,1024]^T.
// Single-stage smem (73.7 KB) + cp.async loads; 2 CTAs/SM interleave.
// 3 passes: Ahi*Bhi + Ahi*Blo + Alo*Bhi, fp32 accumulators.
// ===========================================================================
#define KC        64
#define NCHUNK    (DM / KC)
#define ROWB      144
#define TILE_B    (128 * ROWB)
#define OFF_AHI   0
#define OFF_ALO   TILE_B
#define OFF_BHI   (2 * TILE_B)
#define OFF_BLO   (3 * TILE_B)
#define GEMM_SMEM (4 * TILE_B)        // 73728 B -> 2 CTAs/SM

__device__ __forceinline__ void issue_stage(
    const __half* __restrict__ Ahi, const __half* __restrict__ Alo,
    const __half* __restrict__ Bhi, const __half* __restrict__ Blo,
    int m0, int n0, int k0, uint32_t sbase, int tid)
{
    #pragma unroll
    for (int v = tid; v < 1024; v += 256) {
        int row = v >> 3, ch = v & 7;
        uint32_t soff = (uint32_t)row * ROWB + (uint32_t)ch * 16;
        size_t ga = (size_t)(m0 + row) * DM + k0 + ch * 8;
        size_t gb = (size_t)(n0 + row) * DM + k0 + ch * 8;
        CP_ASYNC16(sbase + OFF_AHI + soff, Ahi + ga);
        CP_ASYNC16(sbase + OFF_ALO + soff, Alo + ga);
        CP_ASYNC16(sbase + OFF_BHI + soff, Bhi + gb);
        CP_ASYNC16(sbase + OFF_BLO + soff, Blo + gb);
    }
}

__device__ __forceinline__ void mma_chunk2(
    uint32_t sb, int warp_m, int warp_n, int lane, float d[4][4][4])
{
    const uint32_t aRow = (uint32_t)(warp_m * 64 + (lane & 15)) * ROWB
                        + ((lane >> 4) & 1) * 16;
    const uint32_t bRow = (uint32_t)(warp_n * 32 + (lane & 7)) * ROWB
                        + ((lane >> 3) & 1) * 16;
    #pragma unroll
    for (int ks = 0; ks < 4; ks++) {
        const uint32_t kb = (uint32_t)ks * 32;
        uint32_t bh[4][2], bl[4][2];
        #pragma unroll
        for (int ni = 0; ni < 4; ni++) {
            uint32_t baddr = sb + OFF_BHI + bRow + (uint32_t)ni * 8 * ROWB + kb;
            asm volatile("ldmatrix.sync.aligned.m8n8.x2.shared.b16 {%0,%1}, [%2];"
                : "=r"(bh[ni][0]), "=r"(bh[ni][1]) : "r"(baddr));
            asm volatile("ldmatrix.sync.aligned.m8n8.x2.shared.b16 {%0,%1}, [%2];"
                : "=r"(bl[ni][0]), "=r"(bl[ni][1]) : "r"(baddr + (OFF_BLO - OFF_BHI)));
        }
        #pragma unroll
        for (int mi = 0; mi < 4; mi++) {
            uint32_t aaddr = sb + OFF_AHI + aRow + (uint32_t)mi * 16 * ROWB + kb;
            uint32_t ah[4], al[4];
            ldsm_x4(ah, aaddr);
            ldsm_x4(al, aaddr + (OFF_ALO - OFF_AHI));
            #pragma unroll
            for (int ni = 0; ni < 4; ni++) {
                mma_f16(d[mi][ni], ah, bh[ni][0], bh[ni][1]);
                mma_f16(d[mi][ni], ah, bl[ni][0], bl[ni][1]);
                mma_f16(d[mi][ni], al, bh[ni][0], bh[ni][1]);
            }
        }
    }
}

__device__ __forceinline__ void gemm_f16_mainloop(
    const __half* __restrict__ Ahi, const __half* __restrict__ Alo,
    const __half* __restrict__ Bhi, const __half* __restrict__ Blo,
    int m0, int n0, uint32_t smem_base,
    int warp_m, int warp_n, int lane, int tid, float d[4][4][4])
{
    for (int c = 0; c < NCHUNK; c++) {
        issue_stage(Ahi, Alo, Bhi, Blo, m0, n0, c * KC, smem_base, tid);
        CP_COMMIT();
        CP_WAIT0();
        __syncthreads();
        mma_chunk2(smem_base, warp_m, warp_n, lane, d);
        __syncthreads();
    }
}

// --------------------------- qkv projection --------------------------------
__global__ __launch_bounds__(256, 2) void qkv_mma_kernel(
    const float* __restrict__ bq, const float* __restrict__ bk,
    const float* __restrict__ bv)
{
    extern __shared__ char smem[];
    const uint32_t smem_base = smem_u32(smem);
    const int tid = threadIdx.x;
    const int lane = tid & 31, w = tid >> 5;
    const int warp_m = w & 1, warp_n = w >> 1;
    const int z = blockIdx.z;

    const __half* Ahi = g_Xhi + (size_t)z * M_ * DM;
    const __half* Alo = g_Xlo + (size_t)z * M_ * DM;
    const __half* Bhi = g_Whi + (size_t)z * DM * DM;
    const __half* Blo = g_Wlo + (size_t)z * DM * DM;
    const float* bias = (z == 0) ? bq : (z == 1) ? bk : bv;
    __half* ghi = (z == 0) ? g_Qhi : (z == 1) ? g_Khi : g_Vhi;
    __half* glo = (z == 0) ? g_Qlo : (z == 1) ? g_Klo : g_Vlo;
    const float scale = (z == 0) ? 0.125f : 1.0f;

    float d[4][4][4];
    #pragma unroll
    for (int i = 0; i < 4; i++)
        #pragma unroll
        for (int j = 0; j < 4; j++)
            #pragma unroll
            for (int k = 0; k < 4; k++) d[i][j][k] = 0.f;

    const int m0 = blockIdx.x * 128;
    const int n0 = blockIdx.y * 128;
    gemm_f16_mainloop(Ahi, Alo, Bhi, Blo, m0, n0, smem_base,
                      warp_m, warp_n, lane, tid, d);

    #pragma unroll
    for (int mi = 0; mi < 4; mi++) {
        int r  = m0 + warp_m * 64 + mi * 16 + (lane >> 2);
        int bb = r >> 11;
        int s  = r & (S_ - 1);
        #pragma unroll
        for (int ni = 0; ni < 4; ni++) {
            int c  = n0 + warp_n * 32 + ni * 8 + (lane & 3) * 2;
            int h  = c >> 6;
            int dd = c & 63;
            size_t idx0 = ((size_t)(bb * H_ + h) * S_ + s) * DK + dd;
            size_t idx1 = idx0 + 8 * DK;
            float x0 = (d[mi][ni][0] + bias[c])     * scale;
            float x1 = (d[mi][ni][1] + bias[c + 1]) * scale;
            float x2 = (d[mi][ni][2] + bias[c])     * scale;
            float x3 = (d[mi][ni][3] + bias[c + 1]) * scale;
            uint32_t lo0, lo1, hi0, hi1;
            hi0 = pack_hl(x0, x1, lo0);
            hi1 = pack_hl(x2, x3, lo1);
            *(uint32_t*)&ghi[idx0] = hi0;
            *(uint32_t*)&glo[idx0] = lo0;
            *(uint32_t*)&ghi[idx1] = hi1;
            *(uint32_t*)&glo[idx1] = lo1;
        }
    }
}

// --------------------------- output projection -----------------------------
__global__ __launch_bounds__(256, 2) void out_mma_kernel(
    const float* __restrict__ bo, float* __restrict__ out)
{
    extern __shared__ char smem[];
    const uint32_t smem_base = smem_u32(smem);
    const int tid = threadIdx.x;
    const int lane = tid & 31, w = tid >> 5;
    const int warp_m = w & 1, warp_n = w >> 1;

    float d[4][4][4];
    #pragma unroll
    for (int i = 0; i < 4; i++)
        #pragma unroll
        for (int j = 0; j < 4; j++)
            #pragma unroll
            for (int k = 0; k < 4; k++) d[i][j][k] = 0.f;

    const int m0 = blockIdx.x * 128;
    const int n0 = blockIdx.y * 128;
    gemm_f16_mainloop(g_ATTNhi, g_ATTNlo,
                      g_Whi + (size_t)3 * DM * DM, g_Wlo + (size_t)3 * DM * DM,
                      m0, n0, smem_base, warp_m, warp_n, lane, tid, d);

    #pragma unroll
    for (int mi = 0; mi < 4; mi++) {
        int r = m0 + warp_m * 64 + mi * 16 + (lane >> 2);
        #pragma unroll
        for (int ni = 0; ni < 4; ni++) {
            int c = n0 + warp_n * 32 + ni * 8 + (lane & 3) * 2;
            float2 v0 = { d[mi][ni][0] + bo[c], d[mi][ni][1] + bo[c + 1] };
            float2 v1 = { d[mi][ni][2] + bo[c], d[mi][ni][3] + bo[c + 1] };
            *(float2*)&out[(size_t)r * DM + c]       = v0;
            *(float2*)&out[(size_t)(r + 8) * DM + c] = v1;
        }
    }
}

// ===========================================================================
// Flash attention: fp16 hi/lo QK (3-pass), plain-fp16 P, 2-pass PV.
// 128 q-rows/CTA, 64-col kv tiles, 8 warps x 16 rows. smem 92,160 B.
// ===========================================================================
#define FROWB    144
#define F_KHI    0
#define F_KLO    (F_KHI + 64 * FROWB)
#define F_VHI    (F_KLO + 64 * FROWB)
#define F_VLO    (F_VHI + 64 * FROWB)
#define F_QHI    (F_VLO + 64 * FROWB)
#define F_QLO    (F_QHI + 128 * FROWB)
#define F_PHI    (F_QLO + 128 * FROWB)
#define FLASH_SMEM (F_PHI + 128 * FROWB)  // 92,160 B -> 2 CTAs/SM

__global__ __launch_bounds__(256, 2) void flash_mma_kernel(const int* __restrict__ mask)
{
    extern __shared__ char fsm[];
    const uint32_t base = smem_u32(fsm);
    const int tid  = threadIdx.x;
    const int lane = tid & 31;
    const int w    = tid >> 5;
    const int q0   = blockIdx.x * 128;
    const int h    = blockIdx.y;
    const int b    = blockIdx.z;

    const __half* Qh = g_Qhi + (size_t)(b * H_ + h) * S_ * DK;
    const __half* Ql = g_Qlo + (size_t)(b * H_ + h) * S_ * DK;
    const __half* Kh = g_Khi + (size_t)(b * H_ + h) * S_ * DK;
    const __half* Kl = g_Klo + (size_t)(b * H_ + h) * S_ * DK;
    const __half* Vh = g_Vhi + (size_t)(b * H_ + h) * S_ * DK;
    const __half* Vl = g_Vlo + (size_t)(b * H_ + h) * S_ * DK;
    const int* Mg = mask + (size_t)b * S_ * S_;

    #pragma unroll
    for (int v = tid; v < 1024; v += 256) {
        int row = v >> 3, ch = v & 7;
        uint32_t off = (uint32_t)row * FROWB + (uint32_t)ch * 16;
        *(uint4*)(fsm + F_QHI + off) = *(const uint4*)(Qh + (size_t)(q0 + row) * DK + ch * 8);
        *(uint4*)(fsm + F_QLO + off) = *(const uint4*)(Ql + (size_t)(q0 + row) * DK + ch * 8);
    }

    const uint32_t qbase = base + F_QHI + (uint32_t)(w * 16 + (lane & 15)) * FROWB
                         + ((lane >> 4) & 1) * 16;
    const uint32_t kbase = base + F_KHI + (uint32_t)(((lane >> 4) & 1) * 8 + (lane & 7)) * FROWB
                         + ((lane >> 3) & 1) * 16;
    const uint32_t pbase = base + F_PHI + (uint32_t)(w * 16 + (lane & 15)) * FROWB
                         + ((lane >> 4) & 1) * 16;
    const uint32_t vbase = base + F_VHI + (uint32_t)(((lane >> 3) & 1) * 8 + (lane & 7)) * FROWB
                         + ((lane >> 4) & 1) * 16;

    float m0r = -1e30f, m1r = -1e30f, l0r = 0.f, l1r = 0.f;
    float o[8][4];
    #pragma unroll
    for (int i = 0; i < 8; i++)
        #pragma unroll
        for (int j = 0; j < 4; j++) o[i][j] = 0.f;

    const int rg0 = q0 + w * 16 + (lane >> 2);
    const int cg  = (lane & 3) * 2;

    for (int n0t = 0; n0t < S_; n0t += 64) {
        #pragma unroll
        for (int v = tid; v < 512; v += 256) {
            int row = v >> 3, ch = v & 7;
            uint32_t off = (uint32_t)row * FROWB + (uint32_t)ch * 16;
            const size_t g = (size_t)(n0t + row) * DK + ch * 8;
            *(uint4*)(fsm + F_KHI + off) = *(const uint4*)(Kh + g);
            *(uint4*)(fsm + F_KLO + off) = *(const uint4*)(Kl + g);
            *(uint4*)(fsm + F_VHI + off) = *(const uint4*)(Vh + g);
            *(uint4*)(fsm + F_VLO + off) = *(const uint4*)(Vl + g);
        }
        __syncthreads();

        // ---- S = (Q/8) K^T : 3-pass fp16 hi/lo ----
        float s[8][4];
        #pragma unroll
        for (int i = 0; i < 8; i++)
            #pragma unroll
            for (int j = 0; j < 4; j++) s[i][j] = 0.f;

        #pragma unroll
        for (int ks = 0; ks < 4; ks++) {
            uint32_t aH[4], aL[4];
            ldsm_x4(aH, qbase + ks * 32);
            ldsm_x4(aL, qbase + (F_QLO - F_QHI) + ks * 32);
            #pragma unroll
            for (int nip = 0; nip < 4; nip++) {
                uint32_t kh[4], kl[4];
                uint32_t ka = kbase + (uint32_t)nip * 16 * FROWB + ks * 32;
                ldsm_x4(kh, ka);
                ldsm_x4(kl, ka + (F_KLO - F_KHI));
                mma_f16(s[2 * nip],     aH, kh[0], kh[1]);
                mma_f16(s[2 * nip],     aH, kl[0], kl[1]);
                mma_f16(s[2 * nip],     aL, kh[0], kh[1]);
                mma_f16(s[2 * nip + 1], aH, kh[2], kh[3]);
                mma_f16(s[2 * nip + 1], aH, kl[2], kl[3]);
                mma_f16(s[2 * nip + 1], aL, kh[2], kh[3]);
            }
        }

        #pragma unroll
        for (int ni = 0; ni < 8; ni++) {
            int c = n0t + ni * 8 + cg;
            int2 mm0 = *(const int2*)(Mg + (size_t)rg0 * S_ + c);
            int2 mm1 = *(const int2*)(Mg + (size_t)(rg0 + 8) * S_ + c);
            if (mm0.x == 0) s[ni][0] = -1e9f;
            if (mm0.y == 0) s[ni][1] = -1e9f;
            if (mm1.x == 0) s[ni][2] = -1e9f;
            if (mm1.y == 0) s[ni][3] = -1e9f;
        }

        float mx0 = -1e30f, mx1 = -1e30f;
        #pragma unroll
        for (int ni = 0; ni < 8; ni++) {
            mx0 = fmaxf(mx0, fmaxf(s[ni][0], s[ni][1]));
            mx1 = fmaxf(mx1, fmaxf(s[ni][2], s[ni][3]));
        }
        mx0 = fmaxf(mx0, __shfl_xor_sync(0xffffffffu, mx0, 1));
        mx0 = fmaxf(mx0, __shfl_xor_sync(0xffffffffu, mx0, 2));
        mx1 = fmaxf(mx1, __shfl_xor_sync(0xffffffffu, mx1, 1));
        mx1 = fmaxf(mx1, __shfl_xor_sync(0xffffffffu, mx1, 2));

        float mn0 = fmaxf(m0r, mx0), mn1 = fmaxf(m1r, mx1);
        float f0 = __expf(m0r - mn0), f1 = __expf(m1r - mn1);
        m0r = mn0; m1r = mn1;

        float sum0 = 0.f, sum1 = 0.f;
        #pragma unroll
        for (int ni = 0; ni < 8; ni++) {
            s[ni][0] = __expf(s[ni][0] - mn0);
            s[ni][1] = __expf(s[ni][1] - mn0);
            s[ni][2] = __expf(s[ni][2] - mn1);
            s[ni][3] = __expf(s[ni][3] - mn1);
            sum0 += s[ni][0] + s[ni][1];
            sum1 += s[ni][2] + s[ni][3];
        }
        sum0 += __shfl_xor_sync(0xffffffffu, sum0, 1);
        sum0 += __shfl_xor_sync(0xffffffffu, sum0, 2);
        sum1 += __shfl_xor_sync(0xffffffffu, sum1, 1);
        sum1 += __shfl_xor_sync(0xffffffffu, sum1, 2);
        l0r = l0r * f0 + sum0;
        l1r = l1r * f1 + sum1;

        #pragma unroll
        for (int ni = 0; ni < 8; ni++) {
            o[ni][0] *= f0; o[ni][1] *= f0;
            o[ni][2] *= f1; o[ni][3] *= f1;
        }

        // ---- stage P as plain fp16 (warp-private rows) ----
        #pragma unroll
        for (int ni = 0; ni < 8; ni++) {
            uint32_t cbyte = (uint32_t)(ni * 8 + cg) * 2;
            uint32_t r0off = (uint32_t)(w * 16 + (lane >> 2)) * FROWB + cbyte;
            *(uint32_t*)(fsm + F_PHI + r0off)             = pack_f16(s[ni][0], s[ni][1]);
            *(uint32_t*)(fsm + F_PHI + r0off + 8 * FROWB) = pack_f16(s[ni][2], s[ni][3]);
        }
        __syncwarp();

        // ---- O += P V : 2-pass (P*Vhi + P*Vlo), V via ldmatrix.trans ----
        #pragma unroll
        for (int ks = 0; ks < 4; ks++) {
            uint32_t pH[4];
            ldsm_x4(pH, pbase + ks * 32);
            #pragma unroll
            for (int nip = 0; nip < 4; nip++) {
                uint32_t vh[4], vl[4];
                uint32_t va = vbase + (uint32_t)ks * 16 * FROWB + (uint32_t)nip * 32;
                ldsm_x4_t(vh, va);
                ldsm_x4_t(vl, va + (F_VLO - F_VHI));
                mma_f16(o[2 * nip],     pH, vh[0], vh[1]);
                mma_f16(o[2 * nip],     pH, vl[0], vl[1]);
                mma_f16(o[2 * nip + 1], pH, vh[2], vh[3]);
                mma_f16(o[2 * nip + 1], pH, vl[2], vl[3]);
            }
        }
        __syncthreads();
    }

    // epilogue: normalize, write attn as fp16 hi/lo (merged-head layout)
    float inv0 = 1.0f / l0r, inv1 = 1.0f / l1r;
    #pragma unroll
    for (int ni = 0; ni < 8; ni++) {
        int dd = h * DK + ni * 8 + cg;
        size_t i0 = (size_t)(b * S_ + rg0) * DM + dd;
        size_t i1 = (size_t)(b * S_ + rg0 + 8) * DM + dd;
        uint32_t lo0, lo1, hi0, hi1;
        hi0 = pack_hl(o[ni][0] * inv0, o[ni][1] * inv0, lo0);
        hi1 = pack_hl(o[ni][2] * inv1, o[ni][3] * inv1, lo1);
        *(uint32_t*)&g_ATTNhi[i0] = hi0;
        *(uint32_t*)&g_ATTNlo[i0] = lo0;
        *(uint32_t*)&g_ATTNhi[i1] = hi1;
        *(uint32_t*)&g_ATTNlo[i1] = lo1;
    }
}

// ===========================================================================
extern "C" void kernel_launch(void* const* d_in, const int* in_sizes, int n_in,
                              void* d_out, int out_size)
{
    (void)in_sizes; (void)n_in; (void)out_size;
    const float* query = (const float*)d_in[0];
    const float* key   = (const float*)d_in[1];
    const float* value = (const float*)d_in[2];
    const int*   mask  = (const int*)d_in[3];
    const float* Wq    = (const float*)d_in[4];
    const float* bq    = (const float*)d_in[5];
    const float* Wk    = (const float*)d_in[6];
    const float* bk    = (const float*)d_in[7];
    const float* Wv    = (const float*)d_in[8];
    const float* bv    = (const float*)d_in[9];
    const float* Wo    = (const float*)d_in[10];
    const float* bo    = (const float*)d_in[11];
    float* out = (float*)d_out;

    cudaFuncSetAttribute(qkv_mma_kernel,
                         cudaFuncAttributeMaxDynamicSharedMemorySize, GEMM_SMEM);
    cudaFuncSetAttribute(out_mma_kernel,
                         cudaFuncAttributeMaxDynamicSharedMemorySize, GEMM_SMEM);
    cudaFuncSetAttribute(flash_mma_kernel,
                         cudaFuncAttributeMaxDynamicSharedMemorySize, FLASH_SMEM);

    // 0) pre-convert inputs and weights to fp16 hi/lo
    dim3 gci((M_ * DM) / 1024, 1, 3);
    conv_in_kernel<<<gci, 256>>>(query, key, value);
    dim3 gcw((DM * DM) / 1024, 1, 4);
    conv_w_kernel<<<gcw, 256>>>(Wq, Wk, Wv, Wo);

    // 1) QKV projections
    dim3 gproj(M_ / 128, DM / 128, 3);
    qkv_mma_kernel<<<gproj, 256, GEMM_SMEM>>>(bq, bk, bv);

    // 2) Flash attention
    dim3 gflash(S_ / 128, H_, B_);
    flash_mma_kernel<<<gflash, 256, FLASH_SMEM>>>(mask);

    // 3) Output projection
    dim3 gout(M_ / 128, DM / 128);
    out_mma_kernel<<<gout, 256, GEMM_SMEM>>>(bo, out);
}

// round 17
// speedup vs baseline: 1.2514x; 1.0887x over previous
#include <cuda_runtime.h>
#include <cuda_fp16.h>
#include <cstdint>

// ---------------------------------------------------------------------------
// MultiHeadedAttention: B=2, S=2048, H=16, d_k=64, d_model=1024, fp32.
// R17: flash L1-pressure cuts -- P kept in registers (C-frag == A-frag
// trick), mask as precomputed bitmask, attn stored as single fp16 with
// 2-pass output projection. fp16 hi/lo elsewhere unchanged.
// ---------------------------------------------------------------------------

#define B_  2
#define S_  2048
#define H_  16
#define DK  64
#define DM  1024
#define M_  (B_ * S_)   // 4096

#define QKV_ELEMS ((size_t)B_ * H_ * S_ * DK)
__device__ __align__(16) __half g_Qhi[QKV_ELEMS];  // pre-scaled by 1/8
__device__ __align__(16) __half g_Qlo[QKV_ELEMS];
__device__ __align__(16) __half g_Khi[QKV_ELEMS];
__device__ __align__(16) __half g_Klo[QKV_ELEMS];
__device__ __align__(16) __half g_Vhi[QKV_ELEMS];
__device__ __align__(16) __half g_Vlo[QKV_ELEMS];

__device__ __align__(16) __half g_Xhi[3 * (size_t)M_ * DM];
__device__ __align__(16) __half g_Xlo[3 * (size_t)M_ * DM];
__device__ __align__(16) __half g_Whi[4 * (size_t)DM * DM];
__device__ __align__(16) __half g_Wlo[4 * (size_t)DM * DM];

__device__ __align__(16) __half g_ATTN[(size_t)M_ * DM];      // single fp16

__device__ __align__(16) uint32_t g_mbits[(size_t)B_ * S_ * (S_ / 32)];  // 2 MB

// ===========================================================================
// helpers
// ===========================================================================
__device__ __forceinline__ uint32_t smem_u32(const void* p) {
    uint32_t a;
    asm("{ .reg .u64 t; cvta.to.shared.u64 t, %1; cvt.u32.u64 %0, t; }"
        : "=r"(a) : "l"(p));
    return a;
}
__device__ __forceinline__ void ldsm_x4(uint32_t (&r)[4], uint32_t addr) {
    asm volatile("ldmatrix.sync.aligned.m8n8.x4.shared.b16 {%0,%1,%2,%3}, [%4];"
        : "=r"(r[0]), "=r"(r[1]), "=r"(r[2]), "=r"(r[3]) : "r"(addr));
}
__device__ __forceinline__ void ldsm_x4_t(uint32_t (&r)[4], uint32_t addr) {
    asm volatile("ldmatrix.sync.aligned.m8n8.x4.trans.shared.b16 {%0,%1,%2,%3}, [%4];"
        : "=r"(r[0]), "=r"(r[1]), "=r"(r[2]), "=r"(r[3]) : "r"(addr));
}
__device__ __forceinline__ void mma_f16(float (&d)[4], const uint32_t (&a)[4],
                                        uint32_t b0, uint32_t b1) {
    asm volatile(
        "mma.sync.aligned.m16n8k16.row.col.f32.f16.f16.f32 "
        "{%0,%1,%2,%3}, {%4,%5,%6,%7}, {%8,%9}, {%0,%1,%2,%3};"
        : "+f"(d[0]), "+f"(d[1]), "+f"(d[2]), "+f"(d[3])
        : "r"(a[0]), "r"(a[1]), "r"(a[2]), "r"(a[3]), "r"(b0), "r"(b1));
}
__device__ __forceinline__ uint32_t pack_hl(float x0, float x1, uint32_t& lo) {
    __half h0 = __float2half_rn(x0), h1 = __float2half_rn(x1);
    __half l0 = __float2half_rn(x0 - __half2float(h0));
    __half l1 = __float2half_rn(x1 - __half2float(h1));
    lo = (uint32_t)__half_as_ushort(l0) | ((uint32_t)__half_as_ushort(l1) << 16);
    return (uint32_t)__half_as_ushort(h0) | ((uint32_t)__half_as_ushort(h1) << 16);
}
__device__ __forceinline__ uint32_t pack_f16(float x0, float x1) {
    return (uint32_t)__half_as_ushort(__float2half_rn(x0))
         | ((uint32_t)__half_as_ushort(__float2half_rn(x1)) << 16);
}

#define CP_ASYNC16(saddr, gptr) \
    asm volatile("cp.async.cg.shared.global [%0], [%1], 16;" \
                 :: "r"(saddr), "l"(gptr))
#define CP_COMMIT() asm volatile("cp.async.commit_group;" ::: "memory")
#define CP_WAIT0()  asm volatile("cp.async.wait_group 0;" ::: "memory")

// ===========================================================================
// conversion kernels
// ===========================================================================
__global__ __launch_bounds__(256) void conv_in_kernel(
    const float* __restrict__ q, const float* __restrict__ k,
    const float* __restrict__ v)
{
    const float* src = (blockIdx.z == 0) ? q : (blockIdx.z == 1) ? k : v;
    __half* hi = g_Xhi + (size_t)blockIdx.z * M_ * DM;
    __half* lo = g_Xlo + (size_t)blockIdx.z * M_ * DM;
    size_t i = ((size_t)blockIdx.x * 256 + threadIdx.x) * 4;
    float4 x = *(const float4*)(src + i);
    uint32_t l0, l1;
    uint32_t h0 = pack_hl(x.x, x.y, l0);
    uint32_t h1 = pack_hl(x.z, x.w, l1);
    *(uint2*)&hi[i] = make_uint2(h0, h1);
    *(uint2*)&lo[i] = make_uint2(l0, l1);
}

__global__ __launch_bounds__(256) void conv_w_kernel(
    const float* __restrict__ wq, const float* __restrict__ wk,
    const float* __restrict__ wv, const float* __restrict__ wo)
{
    const float* src = (blockIdx.z == 0) ? wq : (blockIdx.z == 1) ? wk
                     : (blockIdx.z == 2) ? wv : wo;
    __half* hi = g_Whi + (size_t)blockIdx.z * DM * DM;
    __half* lo = g_Wlo + (size_t)blockIdx.z * DM * DM;
    size_t i = ((size_t)blockIdx.x * 256 + threadIdx.x) * 4;
    float4 x = *(const float4*)(src + i);
    uint32_t l0, l1;
    uint32_t h0 = pack_hl(x.x, x.y, l0);
    uint32_t h1 = pack_hl(x.z, x.w, l1);
    *(uint2*)&hi[i] = make_uint2(h0, h1);
    *(uint2*)&lo[i] = make_uint2(l0, l1);
}

// mask -> bitmask: one warp produces one uint32 word (ballot)
__global__ __launch_bounds__(256) void mask_bits_kernel(const int* __restrict__ mask)
{
    size_t word = ((size_t)blockIdx.x * 256 + threadIdx.x) >> 5;
    int lane = threadIdx.x & 31;
    uint32_t bit = (mask[word * 32 + lane] != 0) ? 1u : 0u;
    uint32_t w = __ballot_sync(0xffffffffu, bit);
    if (lane == 0) g_mbits[word] = w;
}

// ===========================================================================
// fp16 GEMM (3-pass, hi/lo A and B): used for qkv. 73.7 KB smem, 2 CTAs/SM.
// ===========================================================================
#define KC        64
#define NCHUNK    (DM / KC)
#define ROWB      144
#define TILE_B    (128 * ROWB)
#define OFF_AHI   0
#define OFF_ALO   TILE_B
#define OFF_BHI   (2 * TILE_B)
#define OFF_BLO   (3 * TILE_B)
#define GEMM_SMEM (4 * TILE_B)        // 73728 B

__device__ __forceinline__ void issue_stage(
    const __half* __restrict__ Ahi, const __half* __restrict__ Alo,
    const __half* __restrict__ Bhi, const __half* __restrict__ Blo,
    int m0, int n0, int k0, uint32_t sbase, int tid)
{
    #pragma unroll
    for (int v = tid; v < 1024; v += 256) {
        int row = v >> 3, ch = v & 7;
        uint32_t soff = (uint32_t)row * ROWB + (uint32_t)ch * 16;
        size_t ga = (size_t)(m0 + row) * DM + k0 + ch * 8;
        size_t gb = (size_t)(n0 + row) * DM + k0 + ch * 8;
        CP_ASYNC16(sbase + OFF_AHI + soff, Ahi + ga);
        CP_ASYNC16(sbase + OFF_ALO + soff, Alo + ga);
        CP_ASYNC16(sbase + OFF_BHI + soff, Bhi + gb);
        CP_ASYNC16(sbase + OFF_BLO + soff, Blo + gb);
    }
}

__device__ __forceinline__ void mma_chunk3(
    uint32_t sb, int warp_m, int warp_n, int lane, float d[4][4][4])
{
    const uint32_t aRow = (uint32_t)(warp_m * 64 + (lane & 15)) * ROWB
                        + ((lane >> 4) & 1) * 16;
    const uint32_t bRow = (uint32_t)(warp_n * 32 + (lane & 7)) * ROWB
                        + ((lane >> 3) & 1) * 16;
    #pragma unroll
    for (int ks = 0; ks < 4; ks++) {
        const uint32_t kb = (uint32_t)ks * 32;
        uint32_t bh[4][2], bl[4][2];
        #pragma unroll
        for (int ni = 0; ni < 4; ni++) {
            uint32_t baddr = sb + OFF_BHI + bRow + (uint32_t)ni * 8 * ROWB + kb;
            asm volatile("ldmatrix.sync.aligned.m8n8.x2.shared.b16 {%0,%1}, [%2];"
                : "=r"(bh[ni][0]), "=r"(bh[ni][1]) : "r"(baddr));
            asm volatile("ldmatrix.sync.aligned.m8n8.x2.shared.b16 {%0,%1}, [%2];"
                : "=r"(bl[ni][0]), "=r"(bl[ni][1]) : "r"(baddr + (OFF_BLO - OFF_BHI)));
        }
        #pragma unroll
        for (int mi = 0; mi < 4; mi++) {
            uint32_t aaddr = sb + OFF_AHI + aRow + (uint32_t)mi * 16 * ROWB + kb;
            uint32_t ah[4], al[4];
            ldsm_x4(ah, aaddr);
            ldsm_x4(al, aaddr + (OFF_ALO - OFF_AHI));
            #pragma unroll
            for (int ni = 0; ni < 4; ni++) {
                mma_f16(d[mi][ni], ah, bh[ni][0], bh[ni][1]);
                mma_f16(d[mi][ni], ah, bl[ni][0], bl[ni][1]);
                mma_f16(d[mi][ni], al, bh[ni][0], bh[ni][1]);
            }
        }
    }
}

// --------------------------- qkv projection --------------------------------
__global__ __launch_bounds__(256, 2) void qkv_mma_kernel(
    const float* __restrict__ bq, const float* __restrict__ bk,
    const float* __restrict__ bv)
{
    extern __shared__ char smem[];
    const uint32_t smem_base = smem_u32(smem);
    const int tid = threadIdx.x;
    const int lane = tid & 31, w = tid >> 5;
    const int warp_m = w & 1, warp_n = w >> 1;
    const int z = blockIdx.z;

    const __half* Ahi = g_Xhi + (size_t)z * M_ * DM;
    const __half* Alo = g_Xlo + (size_t)z * M_ * DM;
    const __half* Bhi = g_Whi + (size_t)z * DM * DM;
    const __half* Blo = g_Wlo + (size_t)z * DM * DM;
    const float* bias = (z == 0) ? bq : (z == 1) ? bk : bv;
    __half* ghi = (z == 0) ? g_Qhi : (z == 1) ? g_Khi : g_Vhi;
    __half* glo = (z == 0) ? g_Qlo : (z == 1) ? g_Klo : g_Vlo;
    const float scale = (z == 0) ? 0.125f : 1.0f;

    float d[4][4][4];
    #pragma unroll
    for (int i = 0; i < 4; i++)
        #pragma unroll
        for (int j = 0; j < 4; j++)
            #pragma unroll
            for (int k = 0; k < 4; k++) d[i][j][k] = 0.f;

    const int m0 = blockIdx.x * 128;
    const int n0 = blockIdx.y * 128;
    for (int c = 0; c < NCHUNK; c++) {
        issue_stage(Ahi, Alo, Bhi, Blo, m0, n0, c * KC, smem_base, tid);
        CP_COMMIT(); CP_WAIT0();
        __syncthreads();
        mma_chunk3(smem_base, warp_m, warp_n, lane, d);
        __syncthreads();
    }

    #pragma unroll
    for (int mi = 0; mi < 4; mi++) {
        int r  = m0 + warp_m * 64 + mi * 16 + (lane >> 2);
        int bb = r >> 11;
        int s  = r & (S_ - 1);
        #pragma unroll
        for (int ni = 0; ni < 4; ni++) {
            int c  = n0 + warp_n * 32 + ni * 8 + (lane & 3) * 2;
            int h  = c >> 6;
            int dd = c & 63;
            size_t idx0 = ((size_t)(bb * H_ + h) * S_ + s) * DK + dd;
            size_t idx1 = idx0 + 8 * DK;
            float x0 = (d[mi][ni][0] + bias[c])     * scale;
            float x1 = (d[mi][ni][1] + bias[c + 1]) * scale;
            float x2 = (d[mi][ni][2] + bias[c])     * scale;
            float x3 = (d[mi][ni][3] + bias[c + 1]) * scale;
            uint32_t lo0, lo1, hi0, hi1;
            hi0 = pack_hl(x0, x1, lo0);
            hi1 = pack_hl(x2, x3, lo1);
            *(uint32_t*)&ghi[idx0] = hi0;
            *(uint32_t*)&glo[idx0] = lo0;
            *(uint32_t*)&ghi[idx1] = hi1;
            *(uint32_t*)&glo[idx1] = lo1;
        }
    }
}

// ------------------- output projection (2-pass, A single fp16) -------------
#define OFF2_A    0
#define OFF2_BHI  TILE_B
#define OFF2_BLO  (2 * TILE_B)
#define GEMM2_SMEM (3 * TILE_B)       // 55296 B

__global__ __launch_bounds__(256, 2) void out_mma_kernel(
    const float* __restrict__ bo, float* __restrict__ out)
{
    extern __shared__ char smem[];
    const uint32_t sb = smem_u32(smem);
    const int tid = threadIdx.x;
    const int lane = tid & 31, w = tid >> 5;
    const int warp_m = w & 1, warp_n = w >> 1;

    const __half* Bhi = g_Whi + (size_t)3 * DM * DM;
    const __half* Blo = g_Wlo + (size_t)3 * DM * DM;

    float d[4][4][4];
    #pragma unroll
    for (int i = 0; i < 4; i++)
        #pragma unroll
        for (int j = 0; j < 4; j++)
            #pragma unroll
            for (int k = 0; k < 4; k++) d[i][j][k] = 0.f;

    const int m0 = blockIdx.x * 128;
    const int n0 = blockIdx.y * 128;

    for (int c = 0; c < NCHUNK; c++) {
        const int k0 = c * KC;
        #pragma unroll
        for (int v = tid; v < 1024; v += 256) {
            int row = v >> 3, ch = v & 7;
            uint32_t soff = (uint32_t)row * ROWB + (uint32_t)ch * 16;
            CP_ASYNC16(sb + OFF2_A + soff,
                       g_ATTN + (size_t)(m0 + row) * DM + k0 + ch * 8);
            CP_ASYNC16(sb + OFF2_BHI + soff,
                       Bhi + (size_t)(n0 + row) * DM + k0 + ch * 8);
            CP_ASYNC16(sb + OFF2_BLO + soff,
                       Blo + (size_t)(n0 + row) * DM + k0 + ch * 8);
        }
        CP_COMMIT(); CP_WAIT0();
        __syncthreads();

        const uint32_t aRow = (uint32_t)(warp_m * 64 + (lane & 15)) * ROWB
                            + ((lane >> 4) & 1) * 16;
        const uint32_t bRow = (uint32_t)(warp_n * 32 + (lane & 7)) * ROWB
                            + ((lane >> 3) & 1) * 16;
        #pragma unroll
        for (int ks = 0; ks < 4; ks++) {
            const uint32_t kb = (uint32_t)ks * 32;
            uint32_t bh[4][2], bl[4][2];
            #pragma unroll
            for (int ni = 0; ni < 4; ni++) {
                uint32_t baddr = sb + OFF2_BHI + bRow + (uint32_t)ni * 8 * ROWB + kb;
                asm volatile("ldmatrix.sync.aligned.m8n8.x2.shared.b16 {%0,%1}, [%2];"
                    : "=r"(bh[ni][0]), "=r"(bh[ni][1]) : "r"(baddr));
                asm volatile("ldmatrix.sync.aligned.m8n8.x2.shared.b16 {%0,%1}, [%2];"
                    : "=r"(bl[ni][0]), "=r"(bl[ni][1]) : "r"(baddr + (OFF2_BLO - OFF2_BHI)));
            }
            #pragma unroll
            for (int mi = 0; mi < 4; mi++) {
                uint32_t aaddr = sb + OFF2_A + aRow + (uint32_t)mi * 16 * ROWB + kb;
                uint32_t ah[4];
                ldsm_x4(ah, aaddr);
                #pragma unroll
                for (int ni = 0; ni < 4; ni++) {
                    mma_f16(d[mi][ni], ah, bh[ni][0], bh[ni][1]);
                    mma_f16(d[mi][ni], ah, bl[ni][0], bl[ni][1]);
                }
            }
        }
        __syncthreads();
    }

    #pragma unroll
    for (int mi = 0; mi < 4; mi++) {
        int r = m0 + warp_m * 64 + mi * 16 + (lane >> 2);
        #pragma unroll
        for (int ni = 0; ni < 4; ni++) {
            int c = n0 + warp_n * 32 + ni * 8 + (lane & 3) * 2;
            float2 v0 = { d[mi][ni][0] + bo[c], d[mi][ni][1] + bo[c + 1] };
            float2 v1 = { d[mi][ni][2] + bo[c], d[mi][ni][3] + bo[c + 1] };
            *(float2*)&out[(size_t)r * DM + c]       = v0;
            *(float2*)&out[(size_t)(r + 8) * DM + c] = v1;
        }
    }
}

// ===========================================================================
// Flash attention: QK 3-pass fp16 hi/lo; P in registers (C-frag == A-frag);
// PV 2-pass; bitmask mask; attn out single fp16. smem 73.7 KB, 2 CTAs/SM.
// ===========================================================================
#define FROWB    144
#define F_KHI    0
#define F_KLO    (F_KHI + 64 * FROWB)
#define F_VHI    (F_KLO + 64 * FROWB)
#define F_VLO    (F_VHI + 64 * FROWB)
#define F_QHI    (F_VLO + 64 * FROWB)
#define F_QLO    (F_QHI + 128 * FROWB)
#define FLASH_SMEM (F_QLO + 128 * FROWB)  // 73728 B

__global__ __launch_bounds__(256, 2) void flash_mma_kernel()
{
    extern __shared__ char fsm[];
    const uint32_t base = smem_u32(fsm);
    const int tid  = threadIdx.x;
    const int lane = tid & 31;
    const int w    = tid >> 5;
    const int q0   = blockIdx.x * 128;
    const int h    = blockIdx.y;
    const int b    = blockIdx.z;

    const __half* Qh = g_Qhi + (size_t)(b * H_ + h) * S_ * DK;
    const __half* Ql = g_Qlo + (size_t)(b * H_ + h) * S_ * DK;
    const __half* Kh = g_Khi + (size_t)(b * H_ + h) * S_ * DK;
    const __half* Kl = g_Klo + (size_t)(b * H_ + h) * S_ * DK;
    const __half* Vh = g_Vhi + (size_t)(b * H_ + h) * S_ * DK;
    const __half* Vl = g_Vlo + (size_t)(b * H_ + h) * S_ * DK;

    #pragma unroll
    for (int v = tid; v < 1024; v += 256) {
        int row = v >> 3, ch = v & 7;
        uint32_t off = (uint32_t)row * FROWB + (uint32_t)ch * 16;
        *(uint4*)(fsm + F_QHI + off) = *(const uint4*)(Qh + (size_t)(q0 + row) * DK + ch * 8);
        *(uint4*)(fsm + F_QLO + off) = *(const uint4*)(Ql + (size_t)(q0 + row) * DK + ch * 8);
    }

    const uint32_t qbase = base + F_QHI + (uint32_t)(w * 16 + (lane & 15)) * FROWB
                         + ((lane >> 4) & 1) * 16;
    const uint32_t kbase = base + F_KHI + (uint32_t)(((lane >> 4) & 1) * 8 + (lane & 7)) * FROWB
                         + ((lane >> 3) & 1) * 16;
    const uint32_t vbase = base + F_VHI + (uint32_t)(((lane >> 3) & 1) * 8 + (lane & 7)) * FROWB
                         + ((lane >> 4) & 1) * 16;

    float m0r = -1e30f, m1r = -1e30f, l0r = 0.f, l1r = 0.f;
    float o[8][4];
    #pragma unroll
    for (int i = 0; i < 8; i++)
        #pragma unroll
        for (int j = 0; j < 4; j++) o[i][j] = 0.f;

    const int rg0 = q0 + w * 16 + (lane >> 2);
    const int cg  = (lane & 3) * 2;

    // bitmask row pointers (uint32 words; n0t/32 is even -> uint2 aligned)
    const uint32_t* mb0 = g_mbits + (size_t)(b * S_ + rg0) * (S_ / 32);
    const uint32_t* mb1 = g_mbits + (size_t)(b * S_ + rg0 + 8) * (S_ / 32);

    for (int n0t = 0; n0t < S_; n0t += 64) {
        #pragma unroll
        for (int v = tid; v < 512; v += 256) {
            int row = v >> 3, ch = v & 7;
            uint32_t off = (uint32_t)row * FROWB + (uint32_t)ch * 16;
            const size_t g = (size_t)(n0t + row) * DK + ch * 8;
            *(uint4*)(fsm + F_KHI + off) = *(const uint4*)(Kh + g);
            *(uint4*)(fsm + F_KLO + off) = *(const uint4*)(Kl + g);
            *(uint4*)(fsm + F_VHI + off) = *(const uint4*)(Vh + g);
            *(uint4*)(fsm + F_VLO + off) = *(const uint4*)(Vl + g);
        }
        __syncthreads();

        // ---- S = (Q/8) K^T : 3-pass fp16 hi/lo ----
        float s[8][4];
        #pragma unroll
        for (int i = 0; i < 8; i++)
            #pragma unroll
            for (int j = 0; j < 4; j++) s[i][j] = 0.f;

        #pragma unroll
        for (int ks = 0; ks < 4; ks++) {
            uint32_t aH[4], aL[4];
            ldsm_x4(aH, qbase + ks * 32);
            ldsm_x4(aL, qbase + (F_QLO - F_QHI) + ks * 32);
            #pragma unroll
            for (int nip = 0; nip < 4; nip++) {
                uint32_t kh[4], kl[4];
                uint32_t ka = kbase + (uint32_t)nip * 16 * FROWB + ks * 32;
                ldsm_x4(kh, ka);
                ldsm_x4(kl, ka + (F_KLO - F_KHI));
                mma_f16(s[2 * nip],     aH, kh[0], kh[1]);
                mma_f16(s[2 * nip],     aH, kl[0], kl[1]);
                mma_f16(s[2 * nip],     aL, kh[0], kh[1]);
                mma_f16(s[2 * nip + 1], aH, kh[2], kh[3]);
                mma_f16(s[2 * nip + 1], aH, kl[2], kl[3]);
                mma_f16(s[2 * nip + 1], aL, kh[2], kh[3]);
            }
        }

        // ---- mask via bitmask: 2 x LDG.64 per thread-tile ----
        {
            uint2 mw0 = *(const uint2*)(mb0 + n0t / 32);
            uint2 mw1 = *(const uint2*)(mb1 + n0t / 32);
            #pragma unroll
            for (int ni = 0; ni < 8; ni++) {
                uint32_t w0 = (ni < 4) ? mw0.x : mw0.y;
                uint32_t w1 = (ni < 4) ? mw1.x : mw1.y;
                int sh = (ni * 8 + cg) & 31;
                if (!((w0 >> sh) & 1u))       s[ni][0] = -1e9f;
                if (!((w0 >> (sh + 1)) & 1u)) s[ni][1] = -1e9f;
                if (!((w1 >> sh) & 1u))       s[ni][2] = -1e9f;
                if (!((w1 >> (sh + 1)) & 1u)) s[ni][3] = -1e9f;
            }
        }

        // ---- online softmax ----
        float mx0 = -1e30f, mx1 = -1e30f;
        #pragma unroll
        for (int ni = 0; ni < 8; ni++) {
            mx0 = fmaxf(mx0, fmaxf(s[ni][0], s[ni][1]));
            mx1 = fmaxf(mx1, fmaxf(s[ni][2], s[ni][3]));
        }
        mx0 = fmaxf(mx0, __shfl_xor_sync(0xffffffffu, mx0, 1));
        mx0 = fmaxf(mx0, __shfl_xor_sync(0xffffffffu, mx0, 2));
        mx1 = fmaxf(mx1, __shfl_xor_sync(0xffffffffu, mx1, 1));
        mx1 = fmaxf(mx1, __shfl_xor_sync(0xffffffffu, mx1, 2));

        float mn0 = fmaxf(m0r, mx0), mn1 = fmaxf(m1r, mx1);
        float f0 = __expf(m0r - mn0), f1 = __expf(m1r - mn1);
        m0r = mn0; m1r = mn1;

        float sum0 = 0.f, sum1 = 0.f;
        #pragma unroll
        for (int ni = 0; ni < 8; ni++) {
            s[ni][0] = __expf(s[ni][0] - mn0);
            s[ni][1] = __expf(s[ni][1] - mn0);
            s[ni][2] = __expf(s[ni][2] - mn1);
            s[ni][3] = __expf(s[ni][3] - mn1);
            sum0 += s[ni][0] + s[ni][1];
            sum1 += s[ni][2] + s[ni][3];
        }
        sum0 += __shfl_xor_sync(0xffffffffu, sum0, 1);
        sum0 += __shfl_xor_sync(0xffffffffu, sum0, 2);
        sum1 += __shfl_xor_sync(0xffffffffu, sum1, 1);
        sum1 += __shfl_xor_sync(0xffffffffu, sum1, 2);
        l0r = l0r * f0 + sum0;
        l1r = l1r * f1 + sum1;

        #pragma unroll
        for (int ni = 0; ni < 8; ni++) {
            o[ni][0] *= f0; o[ni][1] *= f0;
            o[ni][2] *= f1; o[ni][3] *= f1;
        }

        // ---- O += P V : P built from C-fragments (no smem round trip) ----
        #pragma unroll
        for (int ks = 0; ks < 4; ks++) {
            uint32_t pA[4];
            pA[0] = pack_f16(s[2 * ks][0],     s[2 * ks][1]);      // (r,   k0-7)
            pA[1] = pack_f16(s[2 * ks][2],     s[2 * ks][3]);      // (r+8, k0-7)
            pA[2] = pack_f16(s[2 * ks + 1][0], s[2 * ks + 1][1]);  // (r,   k8-15)
            pA[3] = pack_f16(s[2 * ks + 1][2], s[2 * ks + 1][3]);  // (r+8, k8-15)
            #pragma unroll
            for (int nip = 0; nip < 4; nip++) {
                uint32_t vh[4], vl[4];
                uint32_t va = vbase + (uint32_t)ks * 16 * FROWB + (uint32_t)nip * 32;
                ldsm_x4_t(vh, va);
                ldsm_x4_t(vl, va + (F_VLO - F_VHI));
                mma_f16(o[2 * nip],     pA, vh[0], vh[1]);
                mma_f16(o[2 * nip],     pA, vl[0], vl[1]);
                mma_f16(o[2 * nip + 1], pA, vh[2], vh[3]);
                mma_f16(o[2 * nip + 1], pA, vl[2], vl[3]);
            }
        }
        __syncthreads();   // protect K/V for next tile
    }

    // epilogue: normalize, write attn as single fp16 (merged-head layout)
    float inv0 = 1.0f / l0r, inv1 = 1.0f / l1r;
    #pragma unroll
    for (int ni = 0; ni < 8; ni++) {
        int dd = h * DK + ni * 8 + cg;
        size_t i0 = (size_t)(b * S_ + rg0) * DM + dd;
        size_t i1 = (size_t)(b * S_ + rg0 + 8) * DM + dd;
        *(uint32_t*)&g_ATTN[i0] = pack_f16(o[ni][0] * inv0, o[ni][1] * inv0);
        *(uint32_t*)&g_ATTN[i1] = pack_f16(o[ni][2] * inv1, o[ni][3] * inv1);
    }
}

// ===========================================================================
extern "C" void kernel_launch(void* const* d_in, const int* in_sizes, int n_in,
                              void* d_out, int out_size)
{
    (void)in_sizes; (void)n_in; (void)out_size;
    const float* query = (const float*)d_in[0];
    const float* key   = (const float*)d_in[1];
    const float* value = (const float*)d_in[2];
    const int*   mask  = (const int*)d_in[3];
    const float* Wq    = (const float*)d_in[4];
    const float* bq    = (const float*)d_in[5];
    const float* Wk    = (const float*)d_in[6];
    const float* bk    = (const float*)d_in[7];
    const float* Wv    = (const float*)d_in[8];
    const float* bv    = (const float*)d_in[9];
    const float* Wo    = (const float*)d_in[10];
    const float* bo    = (const float*)d_in[11];
    float* out = (float*)d_out;

    cudaFuncSetAttribute(qkv_mma_kernel,
                         cudaFuncAttributeMaxDynamicSharedMemorySize, GEMM_SMEM);
    cudaFuncSetAttribute(out_mma_kernel,
                         cudaFuncAttributeMaxDynamicSharedMemorySize, GEMM2_SMEM);
    cudaFuncSetAttribute(flash_mma_kernel,
                         cudaFuncAttributeMaxDynamicSharedMemorySize, FLASH_SMEM);

    // 0) pre-convert inputs/weights + pack mask bits
    dim3 gci((M_ * DM) / 1024, 1, 3);
    conv_in_kernel<<<gci, 256>>>(query, key, value);
    dim3 gcw((DM * DM) / 1024, 1, 4);
    conv_w_kernel<<<gcw, 256>>>(Wq, Wk, Wv, Wo);
    mask_bits_kernel<<<(B_ * S_ * (S_ / 32)) / 8, 256>>>(mask);

    // 1) QKV projections
    dim3 gproj(M_ / 128, DM / 128, 3);
    qkv_mma_kernel<<<gproj, 256, GEMM_SMEM>>>(bq, bk, bv);

    // 2) Flash attention
    dim3 gflash(S_ / 128, H_, B_);
    flash_mma_kernel<<<gflash, 256, FLASH_SMEM>>>();

    // 3) Output projection
    dim3 gout(M_ / 128, DM / 128);
    out_mma_kernel<<<gout, 256, GEMM2_SMEM>>>(bo, out);
}